// round 9
// baseline (speedup 1.0000x reference)
#include <cuda_runtime.h>

#define BATCH        16384
#define NUM_FIELDS   20
#define NUM_FEATURES 100000
#define LATENT_DIM   64

// ONE sample per warp; per iteration the warp gathers TWO fields:
// half-warp 0 -> even field, half-warp 1 -> odd field. Each of the 16 lanes
// in a half owns 4 of the 64 dims -> LDG.128 per row, 10 loads per lane in
// two bursts of 5 (MLP_p1=5, the measured contention sweet spot).
// 16384 warps -> ~64 resident warps/SM (regs=32 fills the RF exactly),
// vs 55/SM for the 2-sample/warp layout.
__global__ __launch_bounds__(256)
void ffm_kernel(const int* __restrict__ x,
                const float* __restrict__ emb,
                float* __restrict__ out)
{
    const int gwarp = (blockIdx.x * blockDim.x + threadIdx.x) >> 5;
    const int lane  = threadIdx.x & 31;
    const int half  = lane >> 4;          // field parity handled by this lane
    const int lh    = lane & 15;          // lane within half: owns dims 4*lh..+3
    const int s     = gwarp;              // batch sample id
    if (s >= BATCH) return;

    // Lanes 0..19 hold the sample's 20 indices.
    int xi = 0;
    if (lane < NUM_FIELDS) xi = __ldg(x + s * NUM_FIELDS + lane);

    float4 sv = make_float4(0.f, 0.f, 0.f, 0.f);  // partial over this lane's 10 fields
    float  sq = 0.f;

    #pragma unroll
    for (int g = 0; g < 10; g += 5) {
        float4 buf[5];
        #pragma unroll
        for (int j = 0; j < 5; ++j) {
            const int f   = 2 * (g + j) + half;       // this half-warp's field
            const int idx = __shfl_sync(0xffffffffu, xi, f, 32);
            const float4* row = reinterpret_cast<const float4*>(
                emb + ((size_t)f * NUM_FEATURES + (size_t)idx) * LATENT_DIM);
            buf[j] = __ldg(row + lh);
        }
        #pragma unroll
        for (int j = 0; j < 5; ++j) {
            const float4 v = buf[j];
            sv.x += v.x;  sv.y += v.y;  sv.z += v.z;  sv.w += v.w;
            sq = fmaf(v.x, v.x, sq);  sq = fmaf(v.y, v.y, sq);
            sq = fmaf(v.z, v.z, sq);  sq = fmaf(v.w, v.w, sq);
        }
        // Keep the next burst's LDGs from being hoisted into this one.
        asm volatile("" ::: "memory");
    }

    // Fold even/odd field partials per dim across the two half-warps.
    float4 sf;
    sf.x = sv.x + __shfl_xor_sync(0xffffffffu, sv.x, 16);
    sf.y = sv.y + __shfl_xor_sync(0xffffffffu, sv.y, 16);
    sf.z = sv.z + __shfl_xor_sync(0xffffffffu, sv.z, 16);
    sf.w = sv.w + __shfl_xor_sync(0xffffffffu, sv.w, 16);

    // Both halves now hold identical per-dim totals, so summing
    // 0.5*||sf||^2 over all 32 lanes yields sum_d s_d^2 exactly once.
    float t = 0.5f * fmaf(sf.x, sf.x, fmaf(sf.y, sf.y,
                     fmaf(sf.z, sf.z, sf.w * sf.w))) - sq;
    int   lin = xi;

    #pragma unroll
    for (int o = 16; o > 0; o >>= 1) {
        t   += __shfl_xor_sync(0xffffffffu, t,   o);
        lin += __shfl_xor_sync(0xffffffffu, lin, o);
    }

    if (lane == 0)
        out[s] = (float)lin + 0.5f * t;
}

extern "C" void kernel_launch(void* const* d_in, const int* in_sizes, int n_in,
                              void* d_out, int out_size)
{
    const int*   x   = (const int*)d_in[0];     // (16384, 20) int32
    // d_in[1] = field_indices (arange(20)) — identity, unused
    const float* emb = (const float*)d_in[2];   // (20, 100000, 64) fp32
    float*       out = (float*)d_out;           // (16384,) fp32

    const int threads = 256;                    // 8 warps = 8 samples / block
    const int blocks  = (BATCH * 32 + threads - 1) / threads;  // 2048
    ffm_kernel<<<blocks, threads>>>(x, emb, out);
}

// round 10
// speedup vs baseline: 1.1257x; 1.1257x over previous
#include <cuda_runtime.h>

#define BATCH        16384
#define NUM_FIELDS   20
#define NUM_FEATURES 100000
#define LATENT_DIM   64

// Best-known layout (R7): two samples per warp, one per half-warp; each lane
// owns 4 of 64 dims -> LDG.128 per embedding row; gathers in bursts of 5
// (MLP_p1=5) separated by scheduling barriers; 8192 warps total.
// This round: 128-thread blocks (4 warps) instead of 256 -> per-SM warp load
// quantizes in 4-warp steps (13-14 blocks/SM, all resident in one wave),
// halving end-of-kernel per-SM load imbalance vs 8-warp blocks.
__global__ __launch_bounds__(128)
void ffm_kernel(const int* __restrict__ x,
                const float* __restrict__ emb,
                float* __restrict__ out)
{
    const int gwarp = (blockIdx.x * blockDim.x + threadIdx.x) >> 5;
    const int lane  = threadIdx.x & 31;
    const int half  = lane >> 4;          // sample within the warp
    const int lh    = lane & 15;          // lane within half-warp
    const int s     = gwarp * 2 + half;   // batch sample id
    if (s >= BATCH) return;

    // 20 indices per half-warp: lanes 0..15 hold fields 0..15,
    // lanes 0..3 additionally hold fields 16..19.
    const int* xrow = x + s * NUM_FIELDS;
    int xi0 = __ldg(xrow + lh);                                    // fields 0..15
    int xi1 = (lh < NUM_FIELDS - 16) ? __ldg(xrow + 16 + lh) : 0;  // fields 16..19

    float4 sv = make_float4(0.f, 0.f, 0.f, 0.f);   // partial of sum_f V[f]
    float  sq = 0.f;                               // partial of sum V^2

    #pragma unroll
    for (int g = 0; g < NUM_FIELDS; g += 5) {
        float4 buf[5];
        #pragma unroll
        for (int j = 0; j < 5; ++j) {
            const int f = g + j;
            int idx;
            if (f < 16) idx = __shfl_sync(0xffffffffu, xi0, f, 16);
            else        idx = __shfl_sync(0xffffffffu, xi1, f - 16, 16);
            const float4* row = reinterpret_cast<const float4*>(
                emb + ((size_t)f * NUM_FEATURES + (size_t)idx) * LATENT_DIM);
            buf[j] = __ldg(row + lh);
        }
        #pragma unroll
        for (int j = 0; j < 5; ++j) {
            const float4 v = buf[j];
            sv.x += v.x;  sv.y += v.y;  sv.z += v.z;  sv.w += v.w;
            sq = fmaf(v.x, v.x, sq);  sq = fmaf(v.y, v.y, sq);
            sq = fmaf(v.z, v.z, sq);  sq = fmaf(v.w, v.w, sq);
        }
        // Keep the next burst's LDGs from being hoisted into this one.
        asm volatile("" ::: "memory");
    }

    float part = fmaf(sv.x, sv.x, fmaf(sv.y, sv.y,
                 fmaf(sv.z, sv.z, sv.w * sv.w))) - sq;
    int   lin  = xi0 + xi1;

    // Reduce within the 16-lane half-warp.
    #pragma unroll
    for (int o = 8; o > 0; o >>= 1) {
        part += __shfl_xor_sync(0xffffffffu, part, o);
        lin  += __shfl_xor_sync(0xffffffffu, lin,  o);
    }

    if (lh == 0)
        out[s] = (float)lin + 0.5f * part;
}

extern "C" void kernel_launch(void* const* d_in, const int* in_sizes, int n_in,
                              void* d_out, int out_size)
{
    const int*   x   = (const int*)d_in[0];     // (16384, 20) int32
    // d_in[1] = field_indices (arange(20)) — identity, unused
    const float* emb = (const float*)d_in[2];   // (20, 100000, 64) fp32
    float*       out = (float*)d_out;           // (16384,) fp32

    const int threads = 128;                    // 4 warps = 8 samples / block
    const int warps   = (BATCH + 1) / 2;        // 8192 warps
    const int blocks  = (warps * 32 + threads - 1) / threads;  // 2048
    ffm_kernel<<<blocks, threads>>>(x, emb, out);
}

// round 11
// speedup vs baseline: 1.1493x; 1.0209x over previous
#include <cuda_runtime.h>

#define BATCH        16384
#define NUM_FIELDS   20
#define NUM_FEATURES 100000
#define LATENT_DIM   64

// Final (R7 operating point — measured optimum over 10 rounds):
// - Two samples per warp, one per half-warp (16 lanes each).
// - Each lane owns 4 of the 64 dims -> one LDG.128 (float4) per embedding row;
//   each row read is 16 lanes x 16 B = 256 B fully coalesced.
// - 8192 warps (1024 x 256-thr blocks) = single resident wave (~55 warps/SM),
//   regs=32 -> full register file, occ ~89%.
// - The 20 gathers issue as TWO bursts of 10 with a scheduling barrier between
//   them: front-batched LDG burst (MLP_p1) 20 -> 10 cuts cross-CTA L1tex
//   wavefront-queue contention and the end-of-kernel straggler spread.
// Effective rate: 84 MB / 10.7 us ~= 7.8 TB/s (~98% of HBM spec, with partial
// L2 residency across CUDA-graph replays). All probed deviations (4 smp/warp,
// LDG.256, 1 smp/warp 2-field, 128-thr blocks, evict_last, 4x5 bursts) were
// neutral or worse.
__global__ __launch_bounds__(256)
void ffm_kernel(const int* __restrict__ x,
                const float* __restrict__ emb,
                float* __restrict__ out)
{
    const int gwarp = (blockIdx.x * blockDim.x + threadIdx.x) >> 5;
    const int lane  = threadIdx.x & 31;
    const int half  = lane >> 4;          // sample within the warp
    const int lh    = lane & 15;          // lane within half-warp
    const int s     = gwarp * 2 + half;   // batch sample id
    if (s >= BATCH) return;

    // 20 indices per half-warp: lanes 0..15 hold fields 0..15,
    // lanes 0..3 additionally hold fields 16..19.
    const int* xrow = x + s * NUM_FIELDS;
    int xi0 = __ldg(xrow + lh);                                    // fields 0..15
    int xi1 = (lh < NUM_FIELDS - 16) ? __ldg(xrow + 16 + lh) : 0;  // fields 16..19

    float4 sv = make_float4(0.f, 0.f, 0.f, 0.f);   // partial of sum_f V[f]
    float  sq = 0.f;                               // partial of sum V^2

    // ---- Burst 1: fields 0..9 ----
    float4 g1[10];
    #pragma unroll
    for (int f = 0; f < 10; ++f) {
        const int idx = __shfl_sync(0xffffffffu, xi0, f, 16);
        const float4* row = reinterpret_cast<const float4*>(
            emb + ((size_t)f * NUM_FEATURES + (size_t)idx) * LATENT_DIM);
        g1[f] = __ldg(row + lh);
    }
    #pragma unroll
    for (int f = 0; f < 10; ++f) {
        const float4 v = g1[f];
        sv.x += v.x;  sv.y += v.y;  sv.z += v.z;  sv.w += v.w;
        sq = fmaf(v.x, v.x, sq);  sq = fmaf(v.y, v.y, sq);
        sq = fmaf(v.z, v.z, sq);  sq = fmaf(v.w, v.w, sq);
    }

    // Prevent ptxas from hoisting burst-2 LDGs above burst-1 consumption.
    asm volatile("" ::: "memory");

    // ---- Burst 2: fields 10..19 ----
    float4 g2[10];
    #pragma unroll
    for (int f = 10; f < NUM_FIELDS; ++f) {
        int idx;
        if (f < 16) idx = __shfl_sync(0xffffffffu, xi0, f, 16);
        else        idx = __shfl_sync(0xffffffffu, xi1, f - 16, 16);
        const float4* row = reinterpret_cast<const float4*>(
            emb + ((size_t)f * NUM_FEATURES + (size_t)idx) * LATENT_DIM);
        g2[f - 10] = __ldg(row + lh);
    }
    #pragma unroll
    for (int f = 0; f < 10; ++f) {
        const float4 v = g2[f];
        sv.x += v.x;  sv.y += v.y;  sv.z += v.z;  sv.w += v.w;
        sq = fmaf(v.x, v.x, sq);  sq = fmaf(v.y, v.y, sq);
        sq = fmaf(v.z, v.z, sq);  sq = fmaf(v.w, v.w, sq);
    }

    float part = fmaf(sv.x, sv.x, fmaf(sv.y, sv.y,
                 fmaf(sv.z, sv.z, sv.w * sv.w))) - sq;
    int   lin  = xi0 + xi1;

    // Reduce within the 16-lane half-warp.
    #pragma unroll
    for (int o = 8; o > 0; o >>= 1) {
        part += __shfl_xor_sync(0xffffffffu, part, o);
        lin  += __shfl_xor_sync(0xffffffffu, lin,  o);
    }

    if (lh == 0)
        out[s] = (float)lin + 0.5f * part;
}

extern "C" void kernel_launch(void* const* d_in, const int* in_sizes, int n_in,
                              void* d_out, int out_size)
{
    const int*   x   = (const int*)d_in[0];     // (16384, 20) int32
    // d_in[1] = field_indices (arange(20)) — identity, unused
    const float* emb = (const float*)d_in[2];   // (20, 100000, 64) fp32
    float*       out = (float*)d_out;           // (16384,) fp32

    const int threads = 256;                    // 8 warps = 16 samples / block
    const int warps   = (BATCH + 1) / 2;        // 8192 warps
    const int blocks  = (warps * 32 + threads - 1) / threads;  // 1024
    ffm_kernel<<<blocks, threads>>>(x, emb, out);
}